// round 16
// baseline (speedup 1.0000x reference)
#include <cuda_runtime.h>
#include <cuda_fp16.h>

#define NT 512

// ---------------- fp16 fragment-linear weight scratch ----------------
// m16n8k16 f16 B-fragments, k32 (2 k16 tiles) packed per uint4:
//   uint index = (nt*KTP + ktp)*128 + lane*4 + kk*2 + reg   (each uint = half2)
//   kbase = (2*ktp+kk)*16 + reg*8 + 2*(lane&3) ; n = nt*8 + (lane>>2)
#define FRAG_TOTAL 346112
__device__ __align__(16) unsigned int g_wfrag[FRAG_TOTAL];

#define WFQ1 0
#define WFK1 14336
#define WFV1 28672
#define WFO1 43008
#define WF11 51200
#define WF21 83968
#define WFQ2 116736
#define WFK2 124928
#define WFV2 133120
#define WFO2 141312
#define WF12 149504
#define WF22 182272
#define WFWF 215040

// big intermediates (L2-resident)
__device__ __align__(16) __half g_P[8192 * 1152];    // block1 qkv projections per (b,tc)
__device__ __align__(16) __half g_x2[8192 * 2048];   // x2 flat, permuted fragment layout

__global__ void prep_weights(const float* __restrict__ q1, const float* __restrict__ k1,
                             const float* __restrict__ v1, const float* __restrict__ o1,
                             const float* __restrict__ f11, const float* __restrict__ f21,
                             const float* __restrict__ q2, const float* __restrict__ k2,
                             const float* __restrict__ v2, const float* __restrict__ o2,
                             const float* __restrict__ f12, const float* __restrict__ f22,
                             const float* __restrict__ wf) {
    int e = blockIdx.x * blockDim.x + threadIdx.x;
    if (e >= FRAG_TOTAL) return;
    const int offs[14] = {0,14336,28672,43008,51200,83968,116736,124928,133120,
                          141312,149504,182272,215040,346112};
    const int Kr[13] = {196,196,196,128,128,512,128,128,128,128,128,512,2048};
    const int Nn[13] = {128,128,128,128,512,128,128,128,128,128,512,128,128};
    int m = 0;
    while (e >= offs[m + 1]) m++;
    const float* W =
        m==0?q1: m==1?k1: m==2?v1: m==3?o1: m==4?f11: m==5?f21:
        m==6?q2: m==7?k2: m==8?v2: m==9?o2: m==10?f12: m==11?f22: wf;
    int l = e - offs[m];
    int N = Nn[m], K = Kr[m];
    int KTPm = (offs[m + 1] - offs[m]) / (16 * N);
    int blk = l >> 7, li = l & 127;
    int lane = li >> 2, kk = (li >> 1) & 1, reg = li & 1;
    int nt = blk / KTPm, ktp = blk - nt * KTPm;
    int kbase = (2 * ktp + kk) * 16 + reg * 8 + 2 * (lane & 3);
    int n = nt * 8 + (lane >> 2);
    float wa = (kbase     < K) ? W[(long)kbase * N + n] : 0.f;
    float wb = (kbase + 1 < K) ? W[(long)(kbase + 1) * N + n] : 0.f;
    __half2 h2 = __floats2half2_rn(wa, wb);
    g_wfrag[e] = *reinterpret_cast<unsigned int*>(&h2);
}

// ---------------- layout helpers ----------------
__device__ __forceinline__ int permc(int l) {
    return (l < 8) ? ((l >> 1) * 4 + (l & 1)) : (((l - 8) >> 1) * 4 + 2 + (l & 1));
}
__device__ __forceinline__ int pcol(int col) {
    return (col >> 4) * 16 + permc(col & 15);
}

__device__ __forceinline__ void mma16(float* d, unsigned a0, unsigned a1,
                                      unsigned a2, unsigned a3,
                                      unsigned b0, unsigned b1) {
    asm volatile("mma.sync.aligned.m16n8k16.row.col.f32.f16.f16.f32 "
                 "{%0,%1,%2,%3}, {%4,%5,%6,%7}, {%8,%9}, {%0,%1,%2,%3};"
                 : "+f"(d[0]), "+f"(d[1]), "+f"(d[2]), "+f"(d[3])
                 : "r"(a0), "r"(a1), "r"(a2), "r"(a3), "r"(b0), "r"(b1));
}

// ================= kernel 0: per-timestep QKV projections for block 1 ======
// grid 128: blockIdx.x = b*2 + half; each CTA handles 64 timesteps.
#define STH_P 240
__global__ void __launch_bounds__(NT, 1)
qkv1_kernel(const float* __restrict__ enc, const float* __restrict__ off) {
    extern __shared__ __half xsm[];
    const int tid = threadIdx.x;
    const int warp = tid >> 5, lane = tid & 31;
    const int r = lane >> 2, c = lane & 3;
    const int b = blockIdx.x >> 1;
    const int th = (blockIdx.x & 1) * 64;   // timestep base

    // stage 64 rows x 224 cols (permuted), coalesced over t
    for (int i = tid; i < 224 * 64; i += NT) {
        int cc = i >> 6, tl = i & 63;
        int t = th + tl;
        float val = 0.f;
        if (cc < 112)      val = enc[((long)b * 112 + cc) * 128 + t];
        else if (cc < 196) val = off[b * 84 + (cc - 112)];
        xsm[tl * STH_P + pcol(cc)] = __float2half_rn(val);
    }
    __syncthreads();

    const uint4* Fq = (const uint4*)(g_wfrag + WFQ1);
    const uint4* Fk = (const uint4*)(g_wfrag + WFK1);
    const uint4* Fv = (const uint4*)(g_wfrag + WFV1);
    const int n0 = warp * 8 + 2 * c;
    __half* Pb = g_P + (long)b * 128 * 1152;

    for (int mt = 0; mt < 4; mt++) {
        float aq[4] = {}, ak[4] = {}, av[4] = {};
        const __half* Ah = xsm + (mt * 16 + r) * STH_P + 4 * c;
        #pragma unroll
        for (int ktp = 0; ktp < 7; ktp++) {
            uint4 bq = Fq[(warp * 7 + ktp) * 32 + lane];
            uint4 bk = Fk[(warp * 7 + ktp) * 32 + lane];
            uint4 bv = Fv[(warp * 7 + ktp) * 32 + lane];
            #pragma unroll
            for (int kk = 0; kk < 2; kk++) {
                int g = (ktp * 2 + kk) * 16;
                uint2 lo = *(const uint2*)(Ah + g);
                uint2 hi = *(const uint2*)(Ah + 8 * STH_P + g);
                mma16(aq, lo.x, hi.x, lo.y, hi.y, kk ? bq.z : bq.x, kk ? bq.w : bq.y);
                mma16(ak, lo.x, hi.x, lo.y, hi.y, kk ? bk.z : bk.x, kk ? bk.w : bk.y);
                mma16(av, lo.x, hi.x, lo.y, hi.y, kk ? bv.z : bv.x, kk ? bv.w : bv.y);
            }
        }
        int row0 = th + mt * 16 + r;
        __half* P0 = Pb + (long)row0 * 1152 + n0;
        __half* P1 = Pb + (long)(row0 + 8) * 1152 + n0;
        *(__half2*)(P0)       = __floats2half2_rn(aq[0], aq[1]);
        *(__half2*)(P1)       = __floats2half2_rn(aq[2], aq[3]);
        *(__half2*)(P0 + 128) = __floats2half2_rn(ak[0], ak[1]);
        *(__half2*)(P1 + 128) = __floats2half2_rn(ak[2], ak[3]);
        *(__half2*)(P0 + 256) = __floats2half2_rn(av[0], av[1]);
        *(__half2*)(P1 + 256) = __floats2half2_rn(av[2], av[3]);
    }
}

// ---------------- encoder shared arena ----------------
#define ST_X    136
#define STH_X   144
#define STH_FF  528     // full-width ff buffer (64 x 512 cols)
#define STG_P   1160    // P-window stage stride (2320B = 580 words, 580%32=4 -> bank-rotated)
#define S_O     0
#define S_H     8704
#define S_X1    17408
#define S_HALF  26112
#define H_OH    0
#define H_HH    9216
#define H_X1H   18432
#define H_FFH   27648   // 64 x 528 halves = 33792 (P stage 19 x 1160 = 22040 aliases here)
#define ARENA_FLOATS 56832   // = 227,328 bytes

__device__ __forceinline__ void warp_reduce2(float& s, float& s2) {
    #pragma unroll
    for (int off = 16; off; off >>= 1) {
        s  += __shfl_xor_sync(0xffffffffu, s,  off);
        s2 += __shfl_xor_sync(0xffffffffu, s2, off);
    }
}

// LayerNorm over 64 rows x 128 cols — vectorized: each thread owns 4 CONTIGUOUS cols.
__device__ void lnorm64(const float* __restrict__ src, const float* __restrict__ resid,
                        const float* __restrict__ g, const float* __restrict__ bta,
                        const float* __restrict__ dst_add,
                        float* __restrict__ dstF, __half* __restrict__ dstH,
                        __half* __restrict__ gdst) {
    int warp = threadIdx.x >> 5, lane = threadIdx.x & 31;
    const int col0 = lane * 4;
    float4 gv = *(const float4*)(g + col0);
    float4 bv = *(const float4*)(bta + col0);
    const int gbase = (col0 >> 4) * 16, l = col0 & 15;
    const int p0 = gbase + permc(l);
    const int p1 = gbase + permc(l + 2);
    #pragma unroll
    for (int rr = 0; rr < 4; rr++) {
        int row = warp + rr * 16;
        float4 x = *(const float4*)(src + row * ST_X + col0);
        if (resid) {
            float4 rx = *(const float4*)(resid + row * ST_X + col0);
            x.x += rx.x; x.y += rx.y; x.z += rx.z; x.w += rx.w;
        }
        float s  = x.x + x.y + x.z + x.w;
        float s2 = x.x * x.x + x.y * x.y + x.z * x.z + x.w * x.w;
        warp_reduce2(s, s2);
        float m   = s * (1.f / 128.f);
        float var = fmaxf(s2 * (1.f / 128.f) - m * m, 0.f);
        float inv = rsqrtf(var + 1e-5f);
        float v0 = (x.x - m) * inv * gv.x + bv.x;
        float v1 = (x.y - m) * inv * gv.y + bv.y;
        float v2 = (x.z - m) * inv * gv.z + bv.z;
        float v3 = (x.w - m) * inv * gv.w + bv.w;
        if (dst_add) {
            float4 da = *(const float4*)(dst_add + row * ST_X + col0);
            v0 += da.x; v1 += da.y; v2 += da.z; v3 += da.w;
        }
        if (dstF) *(float4*)(dstF + row * ST_X + col0) = make_float4(v0, v1, v2, v3);
        if (dstH) {
            *(__half2*)(dstH + row * STH_X + p0) = __floats2half2_rn(v0, v1);
            *(__half2*)(dstH + row * STH_X + p1) = __floats2half2_rn(v2, v3);
        }
        if (gdst) {
            int sq = row >> 4, w = row & 15;
            __half* gp = gdst + (long)sq * 2048 + w * 128;
            *(__half2*)(gp + p0) = __floats2half2_rn(v0, v1);
            *(__half2*)(gp + p1) = __floats2half2_rn(v2, v3);
        }
    }
}

// One transformer block over 4 sequences. GATHER: q/k/v gathered from smem-staged P window.
template<bool GATHER>
__device__ void run_block(float* arena, const __half* __restrict__ Xh,
                          const __half* __restrict__ Pbase, int t0,
                          const float* __restrict__ resid,
                          const uint4* __restrict__ Fq, const uint4* __restrict__ Fk,
                          const uint4* __restrict__ Fv, const uint4* __restrict__ Fo,
                          const uint4* __restrict__ F1, const uint4* __restrict__ F2,
                          const float* __restrict__ bo, const float* __restrict__ bf1,
                          const float* __restrict__ bf2,
                          const float* __restrict__ g1, const float* __restrict__ b1v,
                          const float* __restrict__ g2, const float* __restrict__ b2v,
                          float* __restrict__ dstF, __half* __restrict__ dstH,
                          __half* __restrict__ gdst) {
    const int warp = threadIdx.x >> 5, lane = threadIdx.x & 31;
    const int r = lane >> 2, c = lane & 3;
    float*  o   = arena + S_O;
    float*  h   = arena + S_H;
    __half* hb  = (__half*)(arena + S_HALF);
    __half* oh  = hb + H_OH;
    __half* hh  = hb + H_HH;
    __half* ffh = hb + H_FFH;

    // ---- QKV + register attention ----
    {
        float aq[4][4], ak[4][4], av[4][4];
        if (GATHER) {
            // stage P window rows i=0..18 (src row clamp(t0-8+i)) into ffh, coalesced
            __half* Ps = ffh;
            for (int i = threadIdx.x; i < 19 * 144; i += NT) {
                int row = i / 144, cg = i - row * 144;
                int tc = min(max(t0 - 8 + row, 0), 127);
                *((uint4*)(Ps + row * STG_P) + cg) =
                    *((const uint4*)(Pbase + (long)tc * 1152) + cg);
            }
            __syncthreads();
            const int n0 = warp * 8 + 2 * c;
            #pragma unroll
            for (int s = 0; s < 4; s++) {
                // gather index i = s + w (clamping baked into staging)
                const __half* Pa = Ps + (s + r) * STG_P + n0;       // w = r
                const __half* Pc = Ps + (s + r + 8) * STG_P + n0;   // w = r+8
                float2 f;
                f = __half22float2(*(const __half2*)(Pa));        aq[s][0]=f.x; aq[s][1]=f.y;
                f = __half22float2(*(const __half2*)(Pc));        aq[s][2]=f.x; aq[s][3]=f.y;
                f = __half22float2(*(const __half2*)(Pa + 128));  ak[s][0]=f.x; ak[s][1]=f.y;
                f = __half22float2(*(const __half2*)(Pc + 128));  ak[s][2]=f.x; ak[s][3]=f.y;
                f = __half22float2(*(const __half2*)(Pa + 256));  av[s][0]=f.x; av[s][1]=f.y;
                f = __half22float2(*(const __half2*)(Pc + 256));  av[s][2]=f.x; av[s][3]=f.y;
            }
        } else {
            #pragma unroll
            for (int s = 0; s < 4; s++)
                #pragma unroll
                for (int i = 0; i < 4; i++) { aq[s][i]=0.f; ak[s][i]=0.f; av[s][i]=0.f; }
            const __half* Ah = Xh + r * STH_X + 4 * c;
            #pragma unroll
            for (int ktp = 0; ktp < 4; ktp++) {
                uint4 bq = Fq[(warp * 4 + ktp) * 32 + lane];
                uint4 bk = Fk[(warp * 4 + ktp) * 32 + lane];
                uint4 bv = Fv[(warp * 4 + ktp) * 32 + lane];
                #pragma unroll
                for (int s = 0; s < 4; s++) {
                    const __half* As = Ah + s * 16 * STH_X;
                    #pragma unroll
                    for (int kk = 0; kk < 2; kk++) {
                        int g = (ktp * 2 + kk) * 16;
                        uint2 lo = *(const uint2*)(As + g);
                        uint2 hi = *(const uint2*)(As + 8 * STH_X + g);
                        mma16(aq[s], lo.x, hi.x, lo.y, hi.y, kk ? bq.z : bq.x, kk ? bq.w : bq.y);
                        mma16(ak[s], lo.x, hi.x, lo.y, hi.y, kk ? bk.z : bk.x, kk ? bk.w : bk.y);
                        mma16(av[s], lo.x, hi.x, lo.y, hi.y, kk ? bv.z : bv.x, kk ? bv.w : bv.y);
                    }
                }
            }
        }
        const float scale = 0.70710678118654752f;
        int gpos = (warp >> 1) * 16 + 4 * c + 2 * (warp & 1);
        #pragma unroll
        for (int s = 0; s < 4; s++) {
            float sumA = 0.f, sumB = 0.f;
            float oA0 = 0.f, oA1 = 0.f, oB0 = 0.f, oB1 = 0.f;
            #pragma unroll
            for (int rp = 0; rp < 8; rp++) {
                int src = rp * 4 + c;
                float k00 = __shfl_sync(0xffffffffu, ak[s][0], src);
                float k01 = __shfl_sync(0xffffffffu, ak[s][1], src);
                float k10 = __shfl_sync(0xffffffffu, ak[s][2], src);
                float k11 = __shfl_sync(0xffffffffu, ak[s][3], src);
                float v00 = __shfl_sync(0xffffffffu, av[s][0], src);
                float v01 = __shfl_sync(0xffffffffu, av[s][1], src);
                float v10 = __shfl_sync(0xffffffffu, av[s][2], src);
                float v11 = __shfl_sync(0xffffffffu, av[s][3], src);
                float eA0 = __expf((aq[s][0] * k00 + aq[s][1] * k01) * scale);
                float eA1 = __expf((aq[s][0] * k10 + aq[s][1] * k11) * scale);
                float eB0 = __expf((aq[s][2] * k00 + aq[s][3] * k01) * scale);
                float eB1 = __expf((aq[s][2] * k10 + aq[s][3] * k11) * scale);
                sumA += eA0 + eA1; sumB += eB0 + eB1;
                oA0 += eA0 * v00 + eA1 * v10; oA1 += eA0 * v01 + eA1 * v11;
                oB0 += eB0 * v00 + eB1 * v10; oB1 += eB0 * v01 + eB1 * v11;
            }
            float iA = 1.f / sumA, iB = 1.f / sumB;
            *(__half2*)(oh + (s * 16 + r) * STH_X + gpos)     = __floats2half2_rn(oA0 * iA, oA1 * iA);
            *(__half2*)(oh + (s * 16 + r + 8) * STH_X + gpos) = __floats2half2_rn(oB0 * iB, oB1 * iB);
        }
    }
    __syncthreads();

    const int sp = warp >> 3, q = warp & 7;

    // ---- WO: warp = (2 nt, 2 seq), KTP=4 ----
    {
        float acc[2][2][4] = {};
        const __half* Ah = oh + (sp * 32 + r) * STH_X + 4 * c;
        #pragma unroll
        for (int ktp = 0; ktp < 4; ktp++) {
            uint4 bb0 = Fo[((2 * q)     * 4 + ktp) * 32 + lane];
            uint4 bb1 = Fo[((2 * q + 1) * 4 + ktp) * 32 + lane];
            #pragma unroll
            for (int s = 0; s < 2; s++) {
                const __half* As = Ah + s * 16 * STH_X;
                #pragma unroll
                for (int kk = 0; kk < 2; kk++) {
                    int g = (ktp * 2 + kk) * 16;
                    uint2 lo = *(const uint2*)(As + g);
                    uint2 hi = *(const uint2*)(As + 8 * STH_X + g);
                    mma16(acc[0][s], lo.x, hi.x, lo.y, hi.y, kk ? bb0.z : bb0.x, kk ? bb0.w : bb0.y);
                    mma16(acc[1][s], lo.x, hi.x, lo.y, hi.y, kk ? bb1.z : bb1.x, kk ? bb1.w : bb1.y);
                }
            }
        }
        #pragma unroll
        for (int j = 0; j < 2; j++) {
            int n0 = (2 * q + j) * 8 + 2 * c;
            float2 bb = *(const float2*)(bo + n0);
            #pragma unroll
            for (int s = 0; s < 2; s++) {
                int row = (sp * 2 + s) * 16 + r;
                *(float2*)(h + row * ST_X + n0)       = make_float2(acc[j][s][0] + bb.x, acc[j][s][1] + bb.y);
                *(float2*)(h + (row + 8) * ST_X + n0) = make_float2(acc[j][s][2] + bb.x, acc[j][s][3] + bb.y);
            }
        }
    }
    __syncthreads();

    lnorm64(h, resid, g1, b1v, nullptr, h, hh, nullptr);
    __syncthreads();

    // ---- FF1: both N-halves into full-width ffh, ONE sync ----
    #pragma unroll
    for (int half = 0; half < 2; half++) {
        float a1a[4][2][4] = {};
        const __half* Ah = hh + (sp * 32 + r) * STH_X + 4 * c;
        #pragma unroll
        for (int ktp = 0; ktp < 4; ktp++) {
            uint4 bb[4];
            #pragma unroll
            for (int j = 0; j < 4; j++)
                bb[j] = F1[((half * 32 + q * 4 + j) * 4 + ktp) * 32 + lane];
            #pragma unroll
            for (int s = 0; s < 2; s++) {
                const __half* As = Ah + s * 16 * STH_X;
                #pragma unroll
                for (int kk = 0; kk < 2; kk++) {
                    int g = (ktp * 2 + kk) * 16;
                    uint2 lo = *(const uint2*)(As + g);
                    uint2 hi = *(const uint2*)(As + 8 * STH_X + g);
                    #pragma unroll
                    for (int j = 0; j < 4; j++)
                        mma16(a1a[j][s], lo.x, hi.x, lo.y, hi.y,
                              kk ? bb[j].z : bb[j].x, kk ? bb[j].w : bb[j].y);
                }
            }
        }
        #pragma unroll
        for (int j = 0; j < 4; j++) {
            int ntl = q * 4 + j;
            int gpos = half * 256 + (ntl >> 1) * 16 + 4 * c + 2 * (ntl & 1);
            float2 bb = *(const float2*)(bf1 + half * 256 + ntl * 8 + 2 * c);
            #pragma unroll
            for (int s = 0; s < 2; s++) {
                int row = (sp * 2 + s) * 16 + r;
                *(__half2*)(ffh + row * STH_FF + gpos) =
                    __floats2half2_rn(fmaxf(a1a[j][s][0] + bb.x, 0.f), fmaxf(a1a[j][s][1] + bb.y, 0.f));
                *(__half2*)(ffh + (row + 8) * STH_FF + gpos) =
                    __floats2half2_rn(fmaxf(a1a[j][s][2] + bb.x, 0.f), fmaxf(a1a[j][s][3] + bb.y, 0.f));
            }
        }
    }
    __syncthreads();

    // ---- FF2: single K=512 sweep (16 k32 steps); epilogue writes o (no inner sync) ----
    {
        float accF2[2][2][4] = {};
        const __half* Ah = ffh + (sp * 32 + r) * STH_FF + 4 * c;
        #pragma unroll
        for (int ktp = 0; ktp < 16; ktp++) {
            uint4 bb0 = F2[((2 * q)     * 16 + ktp) * 32 + lane];
            uint4 bb1 = F2[((2 * q + 1) * 16 + ktp) * 32 + lane];
            #pragma unroll
            for (int s = 0; s < 2; s++) {
                const __half* As = Ah + s * 16 * STH_FF;
                #pragma unroll
                for (int kk = 0; kk < 2; kk++) {
                    int g = (ktp * 2 + kk) * 16;
                    uint2 lo = *(const uint2*)(As + g);
                    uint2 hi = *(const uint2*)(As + 8 * STH_FF + g);
                    mma16(accF2[0][s], lo.x, hi.x, lo.y, hi.y, kk ? bb0.z : bb0.x, kk ? bb0.w : bb0.y);
                    mma16(accF2[1][s], lo.x, hi.x, lo.y, hi.y, kk ? bb1.z : bb1.x, kk ? bb1.w : bb1.y);
                }
            }
        }
        // o is disjoint from ffh: no barrier needed before the epilogue stores
        #pragma unroll
        for (int j = 0; j < 2; j++) {
            int n0 = (2 * q + j) * 8 + 2 * c;
            float2 bb = *(const float2*)(bf2 + n0);
            #pragma unroll
            for (int s = 0; s < 2; s++) {
                int row = (sp * 2 + s) * 16 + r;
                *(float2*)(o + row * ST_X + n0)       = make_float2(accF2[j][s][0] + bb.x, accF2[j][s][1] + bb.y);
                *(float2*)(o + (row + 8) * ST_X + n0) = make_float2(accF2[j][s][2] + bb.x, accF2[j][s][3] + bb.y);
            }
        }
    }
    __syncthreads();

    lnorm64(o, h, g2, b2v, resid, dstF, dstH, gdst);
    __syncthreads();
}

__global__ void __launch_bounds__(NT, 1)
encoder_kernel(const float* __restrict__ b1_bo, const float* __restrict__ b1_bf1,
               const float* __restrict__ b1_bf2,
               const float* __restrict__ b1_g1, const float* __restrict__ b1_b1,
               const float* __restrict__ b1_g2, const float* __restrict__ b1_b2,
               const float* __restrict__ b2_bo, const float* __restrict__ b2_bf1,
               const float* __restrict__ b2_bf2,
               const float* __restrict__ b2_g1, const float* __restrict__ b2_b1,
               const float* __restrict__ b2_g2, const float* __restrict__ b2_b2) {
    extern __shared__ float arena[];
    const int b = blockIdx.x >> 5;
    const int t0 = (blockIdx.x & 31) << 2;

    __half* hb  = (__half*)(arena + S_HALF);
    __half* x1h = hb + H_X1H;
    float*  x1  = arena + S_X1;
    const __half* Pbase = g_P + (long)b * 128 * 1152;
    __half* gx2 = g_x2 + (long)(b * 128 + t0) * 2048;

    const unsigned* G = g_wfrag;
    run_block<true>(arena, nullptr, Pbase, t0, nullptr,
                    nullptr, nullptr, nullptr, (const uint4*)(G + WFO1),
                    (const uint4*)(G + WF11), (const uint4*)(G + WF21),
                    b1_bo, b1_bf1, b1_bf2, b1_g1, b1_b1, b1_g2, b1_b2,
                    x1, x1h, nullptr);

    run_block<false>(arena, x1h, nullptr, 0, x1,
                     (const uint4*)(G + WFQ2), (const uint4*)(G + WFK2),
                     (const uint4*)(G + WFV2), (const uint4*)(G + WFO2),
                     (const uint4*)(G + WF12), (const uint4*)(G + WF22),
                     b2_bo, b2_bf1, b2_bf2, b2_g1, b2_b1, b2_g2, b2_b2,
                     nullptr, nullptr, gx2);
}

// ================= kernel 2: final projection GEMM (r12 config) ============
// grid 512 (16-row m-tiles), 512 threads: warp = (kh = K-half, q = nt pair).
// kh=1 warps store partials to smem; kh=0 reduce + write.
#define STH_F 2064
#define FIN_SMEM (16 * STH_F * 2 + 2048 * 4)   // A tile + reduce scratch
__global__ void __launch_bounds__(512)
final_kernel(const float* __restrict__ bf, float* __restrict__ out) {
    extern __shared__ __half fs[];
    float* scr = (float*)(fs + 16 * STH_F);   // 2048 floats
    const int tid = threadIdx.x;
    const int warp = tid >> 5, lane = tid & 31;
    const int r = lane >> 2, c = lane & 3;
    const int kh = warp >> 3, q = warp & 7;
    const int seq0 = blockIdx.x * 16;

    // stage A tile (16 x 2048) into smem at stride 2064
    for (int i = tid; i < 4096; i += 512) {
        int row = i >> 8, cg = i & 255;
        const uint4* src = (const uint4*)(g_x2 + (long)(seq0 + row) * 2048) + cg;
        *((uint4*)(fs + row * STH_F) + cg) = *src;
    }
    __syncthreads();

    const uint4* Fw = (const uint4*)(g_wfrag + WFWF);
    float acc[2][4] = {};
    const __half* Ah = fs + r * STH_F + 4 * c;
    #pragma unroll 4
    for (int ktl = 0; ktl < 32; ktl++) {
        int ktg = kh * 32 + ktl;
        uint4 bb0 = Fw[((2 * q)     * 64 + ktg) * 32 + lane];
        uint4 bb1 = Fw[((2 * q + 1) * 64 + ktg) * 32 + lane];
        #pragma unroll
        for (int kk = 0; kk < 2; kk++) {
            int g = (ktg * 2 + kk) * 16;
            uint2 lo = *(const uint2*)(Ah + g);
            uint2 hi = *(const uint2*)(Ah + 8 * STH_F + g);
            mma16(acc[0], lo.x, hi.x, lo.y, hi.y, kk ? bb0.z : bb0.x, kk ? bb0.w : bb0.y);
            mma16(acc[1], lo.x, hi.x, lo.y, hi.y, kk ? bb1.z : bb1.x, kk ? bb1.w : bb1.y);
        }
    }
    if (kh == 1) {
        #pragma unroll
        for (int j = 0; j < 2; j++) {
            float* sp = scr + ((2 * q + j) * 32 + lane) * 4;
            sp[0] = acc[j][0]; sp[1] = acc[j][1]; sp[2] = acc[j][2]; sp[3] = acc[j][3];
        }
    }
    __syncthreads();
    if (kh == 0) {
        const int b = seq0 >> 7;
        const int tbase = seq0 & 127;
        #pragma unroll
        for (int j = 0; j < 2; j++) {
            const float* sp = scr + ((2 * q + j) * 32 + lane) * 4;
            int n0 = (2 * q + j) * 8 + 2 * c;
            float bf0 = bf[n0], bf1 = bf[n0 + 1];
            out[((long)b * 128 + n0)     * 128 + tbase + r]     = acc[j][0] + sp[0] + bf0;
            out[((long)b * 128 + n0 + 1) * 128 + tbase + r]     = acc[j][1] + sp[1] + bf1;
            out[((long)b * 128 + n0)     * 128 + tbase + r + 8] = acc[j][2] + sp[2] + bf0;
            out[((long)b * 128 + n0 + 1) * 128 + tbase + r + 8] = acc[j][3] + sp[3] + bf1;
        }
    }
}

extern "C" void kernel_launch(void* const* d_in, const int* in_sizes, int n_in,
                              void* d_out, int out_size) {
    (void)in_sizes; (void)n_in; (void)out_size;
    const float* p[30];
    for (int i = 0; i < 30; i++) p[i] = (const float*)d_in[i];

    static bool attr_set = false;
    if (!attr_set) {
        cudaFuncSetAttribute(qkv1_kernel, cudaFuncAttributeMaxDynamicSharedMemorySize,
                             64 * STH_P * (int)sizeof(__half));
        cudaFuncSetAttribute(encoder_kernel, cudaFuncAttributeMaxDynamicSharedMemorySize,
                             ARENA_FLOATS * (int)sizeof(float));
        cudaFuncSetAttribute(final_kernel, cudaFuncAttributeMaxDynamicSharedMemorySize,
                             FIN_SMEM);
        attr_set = true;
    }

    prep_weights<<<(FRAG_TOTAL + 255) / 256, 256>>>(
        p[2], p[3], p[4], p[5], p[7], p[9],
        p[15], p[16], p[17], p[18], p[20], p[22], p[28]);

    qkv1_kernel<<<128, NT, 64 * STH_P * sizeof(__half)>>>(p[0], p[1]);

    encoder_kernel<<<2048, NT, ARENA_FLOATS * sizeof(float)>>>(
        p[6],  p[8],  p[10], p[11], p[12], p[13], p[14],
        p[19], p[21], p[23], p[24], p[25], p[26], p[27]);

    final_kernel<<<512, 512, FIN_SMEM>>>(p[29], (float*)d_out);
}

// round 17
// speedup vs baseline: 1.0344x; 1.0344x over previous
#include <cuda_runtime.h>
#include <cuda_fp16.h>

#define NT 512

// ---------------- fp16 fragment-linear weight scratch ----------------
// m16n8k16 f16 B-fragments, k32 (2 k16 tiles) packed per uint4:
//   uint index = (nt*KTP + ktp)*128 + lane*4 + kk*2 + reg   (each uint = half2)
//   kbase = (2*ktp+kk)*16 + reg*8 + 2*(lane&3) ; n = nt*8 + (lane>>2)
#define FRAG_TOTAL 346112
__device__ __align__(16) unsigned int g_wfrag[FRAG_TOTAL];

#define WFQ1 0
#define WFK1 14336
#define WFV1 28672
#define WFO1 43008
#define WF11 51200
#define WF21 83968
#define WFQ2 116736
#define WFK2 124928
#define WFV2 133120
#define WFO2 141312
#define WF12 149504
#define WF22 182272
#define WFWF 215040

// big intermediates (L2-resident)
__device__ __align__(16) __half g_P[8192 * 1152];    // block1 qkv projections per (b,tc)
__device__ __align__(16) __half g_x2[8192 * 2048];   // x2 flat, permuted fragment layout

__global__ void prep_weights(const float* __restrict__ q1, const float* __restrict__ k1,
                             const float* __restrict__ v1, const float* __restrict__ o1,
                             const float* __restrict__ f11, const float* __restrict__ f21,
                             const float* __restrict__ q2, const float* __restrict__ k2,
                             const float* __restrict__ v2, const float* __restrict__ o2,
                             const float* __restrict__ f12, const float* __restrict__ f22,
                             const float* __restrict__ wf) {
    int e = blockIdx.x * blockDim.x + threadIdx.x;
    if (e >= FRAG_TOTAL) return;
    const int offs[14] = {0,14336,28672,43008,51200,83968,116736,124928,133120,
                          141312,149504,182272,215040,346112};
    const int Kr[13] = {196,196,196,128,128,512,128,128,128,128,128,512,2048};
    const int Nn[13] = {128,128,128,128,512,128,128,128,128,128,512,128,128};
    int m = 0;
    while (e >= offs[m + 1]) m++;
    const float* W =
        m==0?q1: m==1?k1: m==2?v1: m==3?o1: m==4?f11: m==5?f21:
        m==6?q2: m==7?k2: m==8?v2: m==9?o2: m==10?f12: m==11?f22: wf;
    int l = e - offs[m];
    int N = Nn[m], K = Kr[m];
    int KTPm = (offs[m + 1] - offs[m]) / (16 * N);
    int blk = l >> 7, li = l & 127;
    int lane = li >> 2, kk = (li >> 1) & 1, reg = li & 1;
    int nt = blk / KTPm, ktp = blk - nt * KTPm;
    int kbase = (2 * ktp + kk) * 16 + reg * 8 + 2 * (lane & 3);
    int n = nt * 8 + (lane >> 2);
    float wa = (kbase     < K) ? W[(long)kbase * N + n] : 0.f;
    float wb = (kbase + 1 < K) ? W[(long)(kbase + 1) * N + n] : 0.f;
    __half2 h2 = __floats2half2_rn(wa, wb);
    g_wfrag[e] = *reinterpret_cast<unsigned int*>(&h2);
}

// ---------------- layout helpers ----------------
__device__ __forceinline__ int permc(int l) {
    return (l < 8) ? ((l >> 1) * 4 + (l & 1)) : (((l - 8) >> 1) * 4 + 2 + (l & 1));
}
__device__ __forceinline__ int pcol(int col) {
    return (col >> 4) * 16 + permc(col & 15);
}

__device__ __forceinline__ void mma16(float* d, unsigned a0, unsigned a1,
                                      unsigned a2, unsigned a3,
                                      unsigned b0, unsigned b1) {
    asm volatile("mma.sync.aligned.m16n8k16.row.col.f32.f16.f16.f32 "
                 "{%0,%1,%2,%3}, {%4,%5,%6,%7}, {%8,%9}, {%0,%1,%2,%3};"
                 : "+f"(d[0]), "+f"(d[1]), "+f"(d[2]), "+f"(d[3])
                 : "r"(a0), "r"(a1), "r"(a2), "r"(a3), "r"(b0), "r"(b1));
}

// ================= kernel 0: per-timestep QKV projections for block 1 ======
// grid 128: blockIdx.x = b*2 + half; each CTA handles 64 timesteps.
#define STH_P 240
__global__ void __launch_bounds__(NT, 1)
qkv1_kernel(const float* __restrict__ enc, const float* __restrict__ off) {
    extern __shared__ __half xsm[];
    const int tid = threadIdx.x;
    const int warp = tid >> 5, lane = tid & 31;
    const int r = lane >> 2, c = lane & 3;
    const int b = blockIdx.x >> 1;
    const int th = (blockIdx.x & 1) * 64;   // timestep base

    // stage 64 rows x 224 cols (permuted), coalesced over t
    for (int i = tid; i < 224 * 64; i += NT) {
        int cc = i >> 6, tl = i & 63;
        int t = th + tl;
        float val = 0.f;
        if (cc < 112)      val = enc[((long)b * 112 + cc) * 128 + t];
        else if (cc < 196) val = off[b * 84 + (cc - 112)];
        xsm[tl * STH_P + pcol(cc)] = __float2half_rn(val);
    }
    __syncthreads();

    const uint4* Fq = (const uint4*)(g_wfrag + WFQ1);
    const uint4* Fk = (const uint4*)(g_wfrag + WFK1);
    const uint4* Fv = (const uint4*)(g_wfrag + WFV1);
    const int n0 = warp * 8 + 2 * c;
    __half* Pb = g_P + (long)b * 128 * 1152;

    for (int mt = 0; mt < 4; mt++) {
        float aq[4] = {}, ak[4] = {}, av[4] = {};
        const __half* Ah = xsm + (mt * 16 + r) * STH_P + 4 * c;
        #pragma unroll
        for (int ktp = 0; ktp < 7; ktp++) {
            uint4 bq = Fq[(warp * 7 + ktp) * 32 + lane];
            uint4 bk = Fk[(warp * 7 + ktp) * 32 + lane];
            uint4 bv = Fv[(warp * 7 + ktp) * 32 + lane];
            #pragma unroll
            for (int kk = 0; kk < 2; kk++) {
                int g = (ktp * 2 + kk) * 16;
                uint2 lo = *(const uint2*)(Ah + g);
                uint2 hi = *(const uint2*)(Ah + 8 * STH_P + g);
                mma16(aq, lo.x, hi.x, lo.y, hi.y, kk ? bq.z : bq.x, kk ? bq.w : bq.y);
                mma16(ak, lo.x, hi.x, lo.y, hi.y, kk ? bk.z : bk.x, kk ? bk.w : bk.y);
                mma16(av, lo.x, hi.x, lo.y, hi.y, kk ? bv.z : bv.x, kk ? bv.w : bv.y);
            }
        }
        int row0 = th + mt * 16 + r;
        __half* P0 = Pb + (long)row0 * 1152 + n0;
        __half* P1 = Pb + (long)(row0 + 8) * 1152 + n0;
        *(__half2*)(P0)       = __floats2half2_rn(aq[0], aq[1]);
        *(__half2*)(P1)       = __floats2half2_rn(aq[2], aq[3]);
        *(__half2*)(P0 + 128) = __floats2half2_rn(ak[0], ak[1]);
        *(__half2*)(P1 + 128) = __floats2half2_rn(ak[2], ak[3]);
        *(__half2*)(P0 + 256) = __floats2half2_rn(av[0], av[1]);
        *(__half2*)(P1 + 256) = __floats2half2_rn(av[2], av[3]);
    }
}

// ---------------- encoder shared arena ----------------
#define ST_X    136
#define STH_X   144
#define STH_FF  528     // full-width ff buffer (64 x 512 cols)
#define S_O     0
#define S_H     8704
#define S_X1    17408
#define S_HALF  26112
#define H_OH    0
#define H_HH    9216
#define H_X1H   18432
#define H_FFH   27648   // 64 x 528 halves = 33792
#define ARENA_FLOATS 56832   // = 227,328 bytes

__device__ __forceinline__ void warp_reduce2(float& s, float& s2) {
    #pragma unroll
    for (int off = 16; off; off >>= 1) {
        s  += __shfl_xor_sync(0xffffffffu, s,  off);
        s2 += __shfl_xor_sync(0xffffffffu, s2, off);
    }
}

// LayerNorm over 64 rows x 128 cols — vectorized: each thread owns 4 CONTIGUOUS cols.
__device__ void lnorm64(const float* __restrict__ src, const float* __restrict__ resid,
                        const float* __restrict__ g, const float* __restrict__ bta,
                        const float* __restrict__ dst_add,
                        float* __restrict__ dstF, __half* __restrict__ dstH,
                        __half* __restrict__ gdst) {
    int warp = threadIdx.x >> 5, lane = threadIdx.x & 31;
    const int col0 = lane * 4;
    float4 gv = *(const float4*)(g + col0);
    float4 bv = *(const float4*)(bta + col0);
    const int gbase = (col0 >> 4) * 16, l = col0 & 15;
    const int p0 = gbase + permc(l);
    const int p1 = gbase + permc(l + 2);
    #pragma unroll
    for (int rr = 0; rr < 4; rr++) {
        int row = warp + rr * 16;
        float4 x = *(const float4*)(src + row * ST_X + col0);
        if (resid) {
            float4 rx = *(const float4*)(resid + row * ST_X + col0);
            x.x += rx.x; x.y += rx.y; x.z += rx.z; x.w += rx.w;
        }
        float s  = x.x + x.y + x.z + x.w;
        float s2 = x.x * x.x + x.y * x.y + x.z * x.z + x.w * x.w;
        warp_reduce2(s, s2);
        float m   = s * (1.f / 128.f);
        float var = fmaxf(s2 * (1.f / 128.f) - m * m, 0.f);
        float inv = rsqrtf(var + 1e-5f);
        float v0 = (x.x - m) * inv * gv.x + bv.x;
        float v1 = (x.y - m) * inv * gv.y + bv.y;
        float v2 = (x.z - m) * inv * gv.z + bv.z;
        float v3 = (x.w - m) * inv * gv.w + bv.w;
        if (dst_add) {
            float4 da = *(const float4*)(dst_add + row * ST_X + col0);
            v0 += da.x; v1 += da.y; v2 += da.z; v3 += da.w;
        }
        if (dstF) *(float4*)(dstF + row * ST_X + col0) = make_float4(v0, v1, v2, v3);
        if (dstH) {
            *(__half2*)(dstH + row * STH_X + p0) = __floats2half2_rn(v0, v1);
            *(__half2*)(dstH + row * STH_X + p1) = __floats2half2_rn(v2, v3);
        }
        if (gdst) {
            int sq = row >> 4, w = row & 15;
            __half* gp = gdst + (long)sq * 2048 + w * 128;
            *(__half2*)(gp + p0) = __floats2half2_rn(v0, v1);
            *(__half2*)(gp + p1) = __floats2half2_rn(v2, v3);
        }
    }
}

// One transformer block over 4 sequences. GATHER: q/k/v loaded from g_P (direct).
template<bool GATHER>
__device__ void run_block(float* arena, const __half* __restrict__ Xh,
                          const __half* __restrict__ Pbase, int t0,
                          const float* __restrict__ resid,
                          const uint4* __restrict__ Fq, const uint4* __restrict__ Fk,
                          const uint4* __restrict__ Fv, const uint4* __restrict__ Fo,
                          const uint4* __restrict__ F1, const uint4* __restrict__ F2,
                          const float* __restrict__ bo, const float* __restrict__ bf1,
                          const float* __restrict__ bf2,
                          const float* __restrict__ g1, const float* __restrict__ b1v,
                          const float* __restrict__ g2, const float* __restrict__ b2v,
                          float* __restrict__ dstF, __half* __restrict__ dstH,
                          __half* __restrict__ gdst) {
    const int warp = threadIdx.x >> 5, lane = threadIdx.x & 31;
    const int r = lane >> 2, c = lane & 3;
    float*  o   = arena + S_O;
    float*  h   = arena + S_H;
    __half* hb  = (__half*)(arena + S_HALF);
    __half* oh  = hb + H_OH;
    __half* hh  = hb + H_HH;
    __half* ffh = hb + H_FFH;

    // ---- QKV + register attention ----
    {
        float aq[4][4], ak[4][4], av[4][4];
        if (GATHER) {
            const int n0 = warp * 8 + 2 * c;
            #pragma unroll
            for (int s = 0; s < 4; s++) {
                int t = t0 + s;
                int tcA = min(max(t + r - 8, 0), 127);
                int tcB = min(max(t + r, 0), 127);
                const __half* Pa = Pbase + (long)tcA * 1152 + n0;
                const __half* Pc = Pbase + (long)tcB * 1152 + n0;
                float2 f;
                f = __half22float2(*(const __half2*)(Pa));        aq[s][0]=f.x; aq[s][1]=f.y;
                f = __half22float2(*(const __half2*)(Pc));        aq[s][2]=f.x; aq[s][3]=f.y;
                f = __half22float2(*(const __half2*)(Pa + 128));  ak[s][0]=f.x; ak[s][1]=f.y;
                f = __half22float2(*(const __half2*)(Pc + 128));  ak[s][2]=f.x; ak[s][3]=f.y;
                f = __half22float2(*(const __half2*)(Pa + 256));  av[s][0]=f.x; av[s][1]=f.y;
                f = __half22float2(*(const __half2*)(Pc + 256));  av[s][2]=f.x; av[s][3]=f.y;
            }
        } else {
            #pragma unroll
            for (int s = 0; s < 4; s++)
                #pragma unroll
                for (int i = 0; i < 4; i++) { aq[s][i]=0.f; ak[s][i]=0.f; av[s][i]=0.f; }
            const __half* Ah = Xh + r * STH_X + 4 * c;
            #pragma unroll
            for (int ktp = 0; ktp < 4; ktp++) {
                uint4 bq = Fq[(warp * 4 + ktp) * 32 + lane];
                uint4 bk = Fk[(warp * 4 + ktp) * 32 + lane];
                uint4 bv = Fv[(warp * 4 + ktp) * 32 + lane];
                #pragma unroll
                for (int s = 0; s < 4; s++) {
                    const __half* As = Ah + s * 16 * STH_X;
                    #pragma unroll
                    for (int kk = 0; kk < 2; kk++) {
                        int g = (ktp * 2 + kk) * 16;
                        uint2 lo = *(const uint2*)(As + g);
                        uint2 hi = *(const uint2*)(As + 8 * STH_X + g);
                        mma16(aq[s], lo.x, hi.x, lo.y, hi.y, kk ? bq.z : bq.x, kk ? bq.w : bq.y);
                        mma16(ak[s], lo.x, hi.x, lo.y, hi.y, kk ? bk.z : bk.x, kk ? bk.w : bk.y);
                        mma16(av[s], lo.x, hi.x, lo.y, hi.y, kk ? bv.z : bv.x, kk ? bv.w : bv.y);
                    }
                }
            }
        }
        const float scale = 0.70710678118654752f;
        int gpos = (warp >> 1) * 16 + 4 * c + 2 * (warp & 1);
        #pragma unroll
        for (int s = 0; s < 4; s++) {
            // pre-scale q: removes the per-score multiply from the softmax path
            float q0 = aq[s][0] * scale, q1 = aq[s][1] * scale;
            float q2 = aq[s][2] * scale, q3 = aq[s][3] * scale;
            float sumA = 0.f, sumB = 0.f;
            float oA0 = 0.f, oA1 = 0.f, oB0 = 0.f, oB1 = 0.f;
            #pragma unroll
            for (int rp = 0; rp < 8; rp++) {
                int src = rp * 4 + c;
                float k00 = __shfl_sync(0xffffffffu, ak[s][0], src);
                float k01 = __shfl_sync(0xffffffffu, ak[s][1], src);
                float k10 = __shfl_sync(0xffffffffu, ak[s][2], src);
                float k11 = __shfl_sync(0xffffffffu, ak[s][3], src);
                float v00 = __shfl_sync(0xffffffffu, av[s][0], src);
                float v01 = __shfl_sync(0xffffffffu, av[s][1], src);
                float v10 = __shfl_sync(0xffffffffu, av[s][2], src);
                float v11 = __shfl_sync(0xffffffffu, av[s][3], src);
                float eA0 = __expf(q0 * k00 + q1 * k01);
                float eA1 = __expf(q0 * k10 + q1 * k11);
                float eB0 = __expf(q2 * k00 + q3 * k01);
                float eB1 = __expf(q2 * k10 + q3 * k11);
                sumA += eA0 + eA1; sumB += eB0 + eB1;
                oA0 += eA0 * v00 + eA1 * v10; oA1 += eA0 * v01 + eA1 * v11;
                oB0 += eB0 * v00 + eB1 * v10; oB1 += eB0 * v01 + eB1 * v11;
            }
            float iA = 1.f / sumA, iB = 1.f / sumB;
            *(__half2*)(oh + (s * 16 + r) * STH_X + gpos)     = __floats2half2_rn(oA0 * iA, oA1 * iA);
            *(__half2*)(oh + (s * 16 + r + 8) * STH_X + gpos) = __floats2half2_rn(oB0 * iB, oB1 * iB);
        }
    }
    __syncthreads();

    const int sp = warp >> 3, q = warp & 7;

    // ---- WO: warp = (2 nt, 2 seq), KTP=4 ----
    {
        float acc[2][2][4] = {};
        const __half* Ah = oh + (sp * 32 + r) * STH_X + 4 * c;
        #pragma unroll
        for (int ktp = 0; ktp < 4; ktp++) {
            uint4 bb0 = Fo[((2 * q)     * 4 + ktp) * 32 + lane];
            uint4 bb1 = Fo[((2 * q + 1) * 4 + ktp) * 32 + lane];
            #pragma unroll
            for (int s = 0; s < 2; s++) {
                const __half* As = Ah + s * 16 * STH_X;
                #pragma unroll
                for (int kk = 0; kk < 2; kk++) {
                    int g = (ktp * 2 + kk) * 16;
                    uint2 lo = *(const uint2*)(As + g);
                    uint2 hi = *(const uint2*)(As + 8 * STH_X + g);
                    mma16(acc[0][s], lo.x, hi.x, lo.y, hi.y, kk ? bb0.z : bb0.x, kk ? bb0.w : bb0.y);
                    mma16(acc[1][s], lo.x, hi.x, lo.y, hi.y, kk ? bb1.z : bb1.x, kk ? bb1.w : bb1.y);
                }
            }
        }
        #pragma unroll
        for (int j = 0; j < 2; j++) {
            int n0 = (2 * q + j) * 8 + 2 * c;
            float2 bb = *(const float2*)(bo + n0);
            #pragma unroll
            for (int s = 0; s < 2; s++) {
                int row = (sp * 2 + s) * 16 + r;
                *(float2*)(h + row * ST_X + n0)       = make_float2(acc[j][s][0] + bb.x, acc[j][s][1] + bb.y);
                *(float2*)(h + (row + 8) * ST_X + n0) = make_float2(acc[j][s][2] + bb.x, acc[j][s][3] + bb.y);
            }
        }
    }
    __syncthreads();

    lnorm64(h, resid, g1, b1v, nullptr, h, hh, nullptr);
    __syncthreads();

    // ---- FF1: both N-halves into full-width ffh, ONE sync ----
    #pragma unroll
    for (int half = 0; half < 2; half++) {
        float a1a[4][2][4] = {};
        const __half* Ah = hh + (sp * 32 + r) * STH_X + 4 * c;
        #pragma unroll
        for (int ktp = 0; ktp < 4; ktp++) {
            uint4 bb[4];
            #pragma unroll
            for (int j = 0; j < 4; j++)
                bb[j] = F1[((half * 32 + q * 4 + j) * 4 + ktp) * 32 + lane];
            #pragma unroll
            for (int s = 0; s < 2; s++) {
                const __half* As = Ah + s * 16 * STH_X;
                #pragma unroll
                for (int kk = 0; kk < 2; kk++) {
                    int g = (ktp * 2 + kk) * 16;
                    uint2 lo = *(const uint2*)(As + g);
                    uint2 hi = *(const uint2*)(As + 8 * STH_X + g);
                    #pragma unroll
                    for (int j = 0; j < 4; j++)
                        mma16(a1a[j][s], lo.x, hi.x, lo.y, hi.y,
                              kk ? bb[j].z : bb[j].x, kk ? bb[j].w : bb[j].y);
                }
            }
        }
        #pragma unroll
        for (int j = 0; j < 4; j++) {
            int ntl = q * 4 + j;
            int gpos = half * 256 + (ntl >> 1) * 16 + 4 * c + 2 * (ntl & 1);
            float2 bb = *(const float2*)(bf1 + half * 256 + ntl * 8 + 2 * c);
            #pragma unroll
            for (int s = 0; s < 2; s++) {
                int row = (sp * 2 + s) * 16 + r;
                *(__half2*)(ffh + row * STH_FF + gpos) =
                    __floats2half2_rn(fmaxf(a1a[j][s][0] + bb.x, 0.f), fmaxf(a1a[j][s][1] + bb.y, 0.f));
                *(__half2*)(ffh + (row + 8) * STH_FF + gpos) =
                    __floats2half2_rn(fmaxf(a1a[j][s][2] + bb.x, 0.f), fmaxf(a1a[j][s][3] + bb.y, 0.f));
            }
        }
    }
    __syncthreads();

    // ---- FF2: single K=512 sweep; epilogue writes o (disjoint, no inner sync) ----
    {
        float accF2[2][2][4] = {};
        const __half* Ah = ffh + (sp * 32 + r) * STH_FF + 4 * c;
        #pragma unroll
        for (int ktp = 0; ktp < 16; ktp++) {
            uint4 bb0 = F2[((2 * q)     * 16 + ktp) * 32 + lane];
            uint4 bb1 = F2[((2 * q + 1) * 16 + ktp) * 32 + lane];
            #pragma unroll
            for (int s = 0; s < 2; s++) {
                const __half* As = Ah + s * 16 * STH_FF;
                #pragma unroll
                for (int kk = 0; kk < 2; kk++) {
                    int g = (ktp * 2 + kk) * 16;
                    uint2 lo = *(const uint2*)(As + g);
                    uint2 hi = *(const uint2*)(As + 8 * STH_FF + g);
                    mma16(accF2[0][s], lo.x, hi.x, lo.y, hi.y, kk ? bb0.z : bb0.x, kk ? bb0.w : bb0.y);
                    mma16(accF2[1][s], lo.x, hi.x, lo.y, hi.y, kk ? bb1.z : bb1.x, kk ? bb1.w : bb1.y);
                }
            }
        }
        #pragma unroll
        for (int j = 0; j < 2; j++) {
            int n0 = (2 * q + j) * 8 + 2 * c;
            float2 bb = *(const float2*)(bf2 + n0);
            #pragma unroll
            for (int s = 0; s < 2; s++) {
                int row = (sp * 2 + s) * 16 + r;
                *(float2*)(o + row * ST_X + n0)       = make_float2(accF2[j][s][0] + bb.x, accF2[j][s][1] + bb.y);
                *(float2*)(o + (row + 8) * ST_X + n0) = make_float2(accF2[j][s][2] + bb.x, accF2[j][s][3] + bb.y);
            }
        }
    }
    __syncthreads();

    lnorm64(o, h, g2, b2v, resid, dstF, dstH, gdst);
    __syncthreads();
}

__global__ void __launch_bounds__(NT, 1)
encoder_kernel(const float* __restrict__ b1_bo, const float* __restrict__ b1_bf1,
               const float* __restrict__ b1_bf2,
               const float* __restrict__ b1_g1, const float* __restrict__ b1_b1,
               const float* __restrict__ b1_g2, const float* __restrict__ b1_b2,
               const float* __restrict__ b2_bo, const float* __restrict__ b2_bf1,
               const float* __restrict__ b2_bf2,
               const float* __restrict__ b2_g1, const float* __restrict__ b2_b1,
               const float* __restrict__ b2_g2, const float* __restrict__ b2_b2) {
    extern __shared__ float arena[];
    const int b = blockIdx.x >> 5;
    const int t0 = (blockIdx.x & 31) << 2;

    __half* hb  = (__half*)(arena + S_HALF);
    __half* x1h = hb + H_X1H;
    float*  x1  = arena + S_X1;
    const __half* Pbase = g_P + (long)b * 128 * 1152;
    __half* gx2 = g_x2 + (long)(b * 128 + t0) * 2048;

    const unsigned* G = g_wfrag;
    run_block<true>(arena, nullptr, Pbase, t0, nullptr,
                    nullptr, nullptr, nullptr, (const uint4*)(G + WFO1),
                    (const uint4*)(G + WF11), (const uint4*)(G + WF21),
                    b1_bo, b1_bf1, b1_bf2, b1_g1, b1_b1, b1_g2, b1_b2,
                    x1, x1h, nullptr);

    run_block<false>(arena, x1h, nullptr, 0, x1,
                     (const uint4*)(G + WFQ2), (const uint4*)(G + WFK2),
                     (const uint4*)(G + WFV2), (const uint4*)(G + WFO2),
                     (const uint4*)(G + WF12), (const uint4*)(G + WF22),
                     b2_bo, b2_bf1, b2_bf2, b2_g1, b2_b1, b2_g2, b2_b2,
                     nullptr, nullptr, gx2);
}

// ================= kernel 2: final projection GEMM (r12 config) ============
// grid 512 (16-row m-tiles), 512 threads: warp = (kh = K-half, q = nt pair).
// kh=1 warps store partials to smem; kh=0 reduce + write.
#define STH_F 2064
#define FIN_SMEM (16 * STH_F * 2 + 2048 * 4)   // A tile + reduce scratch
__global__ void __launch_bounds__(512)
final_kernel(const float* __restrict__ bf, float* __restrict__ out) {
    extern __shared__ __half fs[];
    float* scr = (float*)(fs + 16 * STH_F);   // 2048 floats
    const int tid = threadIdx.x;
    const int warp = tid >> 5, lane = tid & 31;
    const int r = lane >> 2, c = lane & 3;
    const int kh = warp >> 3, q = warp & 7;
    const int seq0 = blockIdx.x * 16;

    // stage A tile (16 x 2048) into smem at stride 2064
    for (int i = tid; i < 4096; i += 512) {
        int row = i >> 8, cg = i & 255;
        const uint4* src = (const uint4*)(g_x2 + (long)(seq0 + row) * 2048) + cg;
        *((uint4*)(fs + row * STH_F) + cg) = *src;
    }
    __syncthreads();

    const uint4* Fw = (const uint4*)(g_wfrag + WFWF);
    float acc[2][4] = {};
    const __half* Ah = fs + r * STH_F + 4 * c;
    #pragma unroll 4
    for (int ktl = 0; ktl < 32; ktl++) {
        int ktg = kh * 32 + ktl;
        uint4 bb0 = Fw[((2 * q)     * 64 + ktg) * 32 + lane];
        uint4 bb1 = Fw[((2 * q + 1) * 64 + ktg) * 32 + lane];
        #pragma unroll
        for (int kk = 0; kk < 2; kk++) {
            int g = (ktg * 2 + kk) * 16;
            uint2 lo = *(const uint2*)(Ah + g);
            uint2 hi = *(const uint2*)(Ah + 8 * STH_F + g);
            mma16(acc[0], lo.x, hi.x, lo.y, hi.y, kk ? bb0.z : bb0.x, kk ? bb0.w : bb0.y);
            mma16(acc[1], lo.x, hi.x, lo.y, hi.y, kk ? bb1.z : bb1.x, kk ? bb1.w : bb1.y);
        }
    }
    if (kh == 1) {
        #pragma unroll
        for (int j = 0; j < 2; j++) {
            float* sp = scr + ((2 * q + j) * 32 + lane) * 4;
            sp[0] = acc[j][0]; sp[1] = acc[j][1]; sp[2] = acc[j][2]; sp[3] = acc[j][3];
        }
    }
    __syncthreads();
    if (kh == 0) {
        const int b = seq0 >> 7;
        const int tbase = seq0 & 127;
        #pragma unroll
        for (int j = 0; j < 2; j++) {
            const float* sp = scr + ((2 * q + j) * 32 + lane) * 4;
            int n0 = (2 * q + j) * 8 + 2 * c;
            float bf0 = bf[n0], bf1 = bf[n0 + 1];
            out[((long)b * 128 + n0)     * 128 + tbase + r]     = acc[j][0] + sp[0] + bf0;
            out[((long)b * 128 + n0 + 1) * 128 + tbase + r]     = acc[j][1] + sp[1] + bf1;
            out[((long)b * 128 + n0)     * 128 + tbase + r + 8] = acc[j][2] + sp[2] + bf0;
            out[((long)b * 128 + n0 + 1) * 128 + tbase + r + 8] = acc[j][3] + sp[3] + bf1;
        }
    }
}

extern "C" void kernel_launch(void* const* d_in, const int* in_sizes, int n_in,
                              void* d_out, int out_size) {
    (void)in_sizes; (void)n_in; (void)out_size;
    const float* p[30];
    for (int i = 0; i < 30; i++) p[i] = (const float*)d_in[i];

    static bool attr_set = false;
    if (!attr_set) {
        cudaFuncSetAttribute(qkv1_kernel, cudaFuncAttributeMaxDynamicSharedMemorySize,
                             64 * STH_P * (int)sizeof(__half));
        cudaFuncSetAttribute(encoder_kernel, cudaFuncAttributeMaxDynamicSharedMemorySize,
                             ARENA_FLOATS * (int)sizeof(float));
        cudaFuncSetAttribute(final_kernel, cudaFuncAttributeMaxDynamicSharedMemorySize,
                             FIN_SMEM);
        attr_set = true;
    }

    prep_weights<<<(FRAG_TOTAL + 255) / 256, 256>>>(
        p[2], p[3], p[4], p[5], p[7], p[9],
        p[15], p[16], p[17], p[18], p[20], p[22], p[28]);

    qkv1_kernel<<<128, NT, 64 * STH_P * sizeof(__half)>>>(p[0], p[1]);

    encoder_kernel<<<2048, NT, ARENA_FLOATS * sizeof(float)>>>(
        p[6],  p[8],  p[10], p[11], p[12], p[13], p[14],
        p[19], p[21], p[23], p[24], p[25], p[26], p[27]);

    final_kernel<<<512, 512, FIN_SMEM>>>(p[29], (float*)d_out);
}